// round 15
// baseline (speedup 1.0000x reference)
#include <cuda_runtime.h>
#include <cstdint>

#define H 200
#define S 2047
#define WW 48
#define MID 1023
#define BSW 14             // sentences per word CTA
#define NCTX 147           // ctx CTAs (147*14 = 2058 >= 2047)
#define LSTRIDE 26         // padded float4 row stride for sentence weight slice
#define HSTRIDE 256        // padded history row (floats)
#define SMEM_SENT (400 * LSTRIDE * 16)

// ---------------- scratch (device globals; no allocation) ----------------
__device__ float4 g_WpackA[6][80000];      // all sets: [k*200 + j] = rows(j,j+200,j+400,j+600) at col k
__device__ float4 g_bias6[6][200];         // combined bih+bhh per gate
__device__ float  g_sent[S * 200];         // sentence embeddings
__device__ float  g_hist[2][1024 * HSTRIDE]; // per-dir L0 hidden history (row t = h0 after step t)
__device__ int    g_flag[2][1024];         // per-dir per-step L0 completion counters (target 200)
__device__ float  g_final[2 * 256];        // final top-layer h per direction
__device__ int    g_dummy_sink;

__device__ __forceinline__ float sigf(float x) { return 1.0f / (1.0f + __expf(-x)); }

__device__ __forceinline__ void st_cluster_f32(uint32_t laddr, int rank, float v) {
    uint32_t ra;
    asm volatile("mapa.shared::cluster.u32 %0, %1, %2;" : "=r"(ra) : "r"(laddr), "r"(rank));
    asm volatile("st.shared::cluster.f32 [%0], %1;" :: "r"(ra), "f"(v) : "memory");
}
__device__ __forceinline__ void red_release_add(int* p) {
    asm volatile("red.release.gpu.global.add.u32 [%0], %1;" :: "l"(p), "r"(1) : "memory");
}
__device__ __forceinline__ int ld_acquire(const int* p) {
    int v; asm volatile("ld.acquire.gpu.global.u32 %0, [%1];" : "=r"(v) : "l"(p) : "memory"); return v;
}
#define CLUSTER_SYNC() do { \
    asm volatile("barrier.cluster.arrive.aligned;" ::: "memory"); \
    asm volatile("barrier.cluster.wait.aligned;"   ::: "memory"); } while (0)

// ---------------- kernel 0: no-op shift (x2: steer ncu -s 5 onto the WORD kernel) ----------------
__global__ void ABHUE_shift_kernel(int v) {
    if (threadIdx.x == 0 && blockIdx.x == 0) g_dummy_sink = v;
}

// ---------------- kernel 1: pack weights / biases, reset flags ----------------
__global__ void ABHUE_pack_kernel(
    const float* __restrict__ cWih, const float* __restrict__ cWhh,
    const float* __restrict__ cbih, const float* __restrict__ cbhh,
    const float* __restrict__ tWih, const float* __restrict__ tWhh,
    const float* __restrict__ tbih, const float* __restrict__ tbhh,
    const float* __restrict__ pWih, const float* __restrict__ pWhh,
    const float* __restrict__ pbih, const float* __restrict__ pbhh,
    const float* __restrict__ qWih, const float* __restrict__ qWhh,
    const float* __restrict__ qbih, const float* __restrict__ qbhh)
{
    const float* Wih6[6] = {cWih, tWih, pWih, pWih + 160000, qWih, qWih + 160000};
    const float* Whh6[6] = {cWhh, tWhh, pWhh, pWhh + 160000, qWhh, qWhh + 160000};
    const float* Bih6[6] = {cbih, tbih, pbih, pbih + 800,    qbih, qbih + 800};
    const float* Bhh6[6] = {cbhh, tbhh, pbhh, pbhh + 800,    qbhh, qbhh + 800};

    int idx = blockIdx.x * blockDim.x + threadIdx.x;
    if (idx < 480000) {
        int set = idx / 80000; int r = idx % 80000;
        int k = r / 200, j = r % 200;
        const float* Wsrc; int kk;
        if (k < 200) { Wsrc = Wih6[set]; kk = k; } else { Wsrc = Whh6[set]; kk = k - 200; }
        g_WpackA[set][k * 200 + j] = make_float4(
            Wsrc[(j      ) * 200 + kk], Wsrc[(200 + j) * 200 + kk],
            Wsrc[(400 + j) * 200 + kk], Wsrc[(600 + j) * 200 + kk]);
    } else if (idx < 481200) {
        int r = idx - 480000; int set = r / 200; int j = r % 200;
        g_bias6[set][j] = make_float4(
            Bih6[set][j      ] + Bhh6[set][j      ],
            Bih6[set][200 + j] + Bhh6[set][200 + j],
            Bih6[set][400 + j] + Bhh6[set][400 + j],
            Bih6[set][600 + j] + Bhh6[set][600 + j]);
    } else if (idx < 481200 + 2048) {
        int r = idx - 481200;
        g_flag[r / 1024][r % 1024] = 0;
    }
}

// ---------------- kernel 2: word-level LSTM — 148 CTAs, 400 threads, prefetch depth 2 (R12-proven) ----------------
__global__ void __launch_bounds__(400, 1) ABHUE_word_kernel(const float* __restrict__ X)
{
    __shared__ __align__(16) float Xs[BSW][200];
    __shared__ __align__(16) float Hs[BSW][200];

    const int c = blockIdx.x, tid = threadIdx.x;
    const int set = (c < NCTX) ? 0 : 1;
    const int s0  = (c < NCTX) ? c * BSW : MID;
    const int nb  = (c < NCTX) ? ((S - s0 < BSW) ? (S - s0) : BSW) : 1;
    const float4* __restrict__ Wp = g_WpackA[set];
    const int j  = tid % 200;
    const int b0 = (tid / 200) * 7;
    const float4 bb = g_bias6[set][j];

    float cst[7];
#pragma unroll
    for (int b = 0; b < 7; b++) cst[b] = 0.f;

    for (int i = tid; i < BSW * 200; i += 400) ((float*)Hs)[i] = 0.f;
    for (int i = tid; i < BSW * 200; i += 400) {
        int b = i / 200, k = i % 200;
        ((float*)Xs)[i] = (b < nb) ? X[(size_t)(s0 + b) * (WW * 200) + k] : 0.f;
    }
    __syncthreads();

    const float* bx = &Xs[0][0] + b0 * 200;
    const float* bh = &Hs[0][0] + b0 * 200;

    for (int t = 0; t < WW; t++) {
        float ai[7], af[7], ag[7], ao[7];
#pragma unroll
        for (int b = 0; b < 7; b++) { ai[b] = bb.x; af[b] = bb.y; ag[b] = bb.z; ao[b] = bb.w; }
        // prefetch pipeline depth 2: a* = row k4, b* = row k4+1
        float4 a0 = Wp[0 * 200 + j], a1 = Wp[1 * 200 + j];
        float4 a2 = Wp[2 * 200 + j], a3 = Wp[3 * 200 + j];
        float4 b0w = Wp[4 * 200 + j], b1w = Wp[5 * 200 + j];
        float4 b2w = Wp[6 * 200 + j], b3w = Wp[7 * 200 + j];
#pragma unroll 1
        for (int k4 = 0; k4 < 100; k4++) {
            float4 n0 = a0, n1 = a1, n2 = a2, n3 = a3;
            if (k4 < 98) {
                const float4* wr = Wp + (4 * k4 + 8) * 200 + j;
                n0 = wr[0];   n1 = wr[200];
                n2 = wr[400]; n3 = wr[600];
            }
            const float* base = (k4 < 50) ? (bx + 4 * k4) : (bh + (4 * k4 - 200));
#pragma unroll
            for (int b = 0; b < 7; b++) {
                float4 xv = *(const float4*)(base + b * 200);
                ai[b] = fmaf(a0.x, xv.x, ai[b]); ai[b] = fmaf(a1.x, xv.y, ai[b]);
                ai[b] = fmaf(a2.x, xv.z, ai[b]); ai[b] = fmaf(a3.x, xv.w, ai[b]);
                af[b] = fmaf(a0.y, xv.x, af[b]); af[b] = fmaf(a1.y, xv.y, af[b]);
                af[b] = fmaf(a2.y, xv.z, af[b]); af[b] = fmaf(a3.y, xv.w, af[b]);
                ag[b] = fmaf(a0.z, xv.x, ag[b]); ag[b] = fmaf(a1.z, xv.y, ag[b]);
                ag[b] = fmaf(a2.z, xv.z, ag[b]); ag[b] = fmaf(a3.z, xv.w, ag[b]);
                ao[b] = fmaf(a0.w, xv.x, ao[b]); ao[b] = fmaf(a1.w, xv.y, ao[b]);
                ao[b] = fmaf(a2.w, xv.z, ao[b]); ao[b] = fmaf(a3.w, xv.w, ao[b]);
            }
            a0 = b0w; a1 = b1w; a2 = b2w; a3 = b3w;
            b0w = n0; b1w = n1; b2w = n2; b3w = n3;
        }
        __syncthreads();
#pragma unroll
        for (int b = 0; b < 7; b++) {
            float iv = sigf(ai[b]), fv = sigf(af[b]);
            float gv = tanhf(ag[b]), ov = sigf(ao[b]);
            cst[b] = fv * cst[b] + iv * gv;
            Hs[b0 + b][j] = ov * tanhf(cst[b]);
        }
        if (t < WW - 1) {
            for (int i = tid; i < BSW * 200; i += 400) {
                int b = i / 200, k = i % 200;
                ((float*)Xs)[i] = (b < nb) ? X[(size_t)(s0 + b) * (WW * 200) + (t + 1) * 200 + k] : 0.f;
            }
        }
        __syncthreads();
    }

#pragma unroll
    for (int b = 0; b < 7; b++) {
        int s = s0 + b0 + b;
        if (b0 + b < nb && !(c < NCTX && s == MID))
            g_sent[s * 200 + j] = Hs[b0 + b][j];
    }
}

// ---------------- kernel 3: sentence-level LSTMs — warp-split x/h overlap, 8-CTA clusters ----------------
// (R12 structure; only delta: no __syncthreads before the cluster barrier — the aligned
//  cluster arrive/wait is itself a block-wide rendezvous with acq/rel semantics)
__global__ void __launch_bounds__(256, 1) __cluster_dims__(8, 1, 1) ABHUE_sent_kernel()
{
    extern __shared__ float4 Wsl[];                 // [k=0..399][jl padded LSTRIDE]
    __shared__ __align__(16) float4 xpart[2][4][32];  // double-buffered x partials
    __shared__ __align__(16) float4 hpart[4][32];     // h partials
    __shared__ __align__(16) float  hbuf[2][200];     // recurrent h, parity double-buffer

    const int cid   = blockIdx.x >> 3;    // 0=prevL0 1=prevL1 2=postL0 3=postL1
    const int rr    = blockIdx.x & 7;
    const int dir   = cid >> 1;
    const int layer = cid & 1;
    const int tid   = threadIdx.x;
    const int wid   = tid >> 5;
    const int lane  = tid & 31;
    const int lanec = (lane < 25) ? lane : 24;

    for (int idx = tid; idx < 400 * 25; idx += 256) {
        int k = idx / 25, jj = idx % 25;
        Wsl[k * LSTRIDE + jj] = g_WpackA[2 + cid][k * 200 + rr * 25 + jj];
    }
    for (int i = tid; i < 400; i += 256) ((float*)hbuf)[i] = 0.f;

    const float4 bb = g_bias6[2 + cid][rr * 25 + lanec];
    float creg = 0.f;
    float* h0g = g_hist[dir];
    int*   flg = g_flag[dir];
    const uint32_t hbase = (uint32_t)__cvta_generic_to_shared(&hbuf[0][0]);
    const int base = wid * 50;               // x-warp k-slice start

    __syncthreads();
    CLUSTER_SYNC();

    if (layer == 0) {
        float xr0 = 0.f, xr1 = 0.f;
        if (wid < 4) {
            int row0 = dir ? 2046 : 0;
            xr0 = g_sent[row0 * 200 + base + lane];
            xr1 = (lane < 18) ? g_sent[row0 * 200 + base + 32 + lane] : 0.f;
            float4 acc = make_float4(0.f, 0.f, 0.f, 0.f);
#pragma unroll
            for (int q = 0; q < 50; q++) {
                float v = (q < 32) ? __shfl_sync(0xFFFFFFFFu, xr0, q)
                                   : __shfl_sync(0xFFFFFFFFu, xr1, q - 32);
                float4 w = Wsl[(base + q) * LSTRIDE + lanec];
                acc.x = fmaf(w.x, v, acc.x); acc.y = fmaf(w.y, v, acc.y);
                acc.z = fmaf(w.z, v, acc.z); acc.w = fmaf(w.w, v, acc.w);
            }
            xpart[0][wid][lane] = acc;
            int row1 = dir ? 2045 : 1;
            xr0 = g_sent[row1 * 200 + base + lane];
            xr1 = (lane < 18) ? g_sent[row1 * 200 + base + 32 + lane] : 0.f;
        }
        __syncthreads();

        for (int i = 0; i < 1024; i++) {
            const int p = i & 1;
            if (wid < 4) {
                float4 acc = make_float4(0.f, 0.f, 0.f, 0.f);
#pragma unroll
                for (int q = 0; q < 50; q++) {
                    float v = (q < 32) ? __shfl_sync(0xFFFFFFFFu, xr0, q)
                                       : __shfl_sync(0xFFFFFFFFu, xr1, q - 32);
                    float4 w = Wsl[(base + q) * LSTRIDE + lanec];
                    acc.x = fmaf(w.x, v, acc.x); acc.y = fmaf(w.y, v, acc.y);
                    acc.z = fmaf(w.z, v, acc.z); acc.w = fmaf(w.w, v, acc.w);
                }
                xpart[p ^ 1][wid][lane] = acc;
                int row2 = dir ? (2046 - (i + 2)) : (i + 2);
                xr0 = g_sent[row2 * 200 + base + lane];
                xr1 = (lane < 18) ? g_sent[row2 * 200 + base + 32 + lane] : 0.f;
            } else {
                const int hb = (wid - 4) * 50;
                float4 acc = make_float4(0.f, 0.f, 0.f, 0.f);
#pragma unroll
                for (int q = 0; q < 50; q++) {
                    float v = hbuf[p ^ 1][hb + q];
                    float4 w = Wsl[(200 + hb + q) * LSTRIDE + lanec];
                    acc.x = fmaf(w.x, v, acc.x); acc.y = fmaf(w.y, v, acc.y);
                    acc.z = fmaf(w.z, v, acc.z); acc.w = fmaf(w.w, v, acc.w);
                }
                hpart[wid - 4][lane] = acc;
                asm volatile("bar.sync 1, 128;" ::: "memory");   // h-warps only
                if (wid == 4 && lane < 25) {
                    float4 s = bb;
#pragma unroll
                    for (int w4 = 0; w4 < 4; w4++) {
                        float4 t1 = xpart[p][w4][lane];
                        s.x += t1.x; s.y += t1.y; s.z += t1.z; s.w += t1.w;
                        float4 t2 = hpart[w4][lane];
                        s.x += t2.x; s.y += t2.y; s.z += t2.z; s.w += t2.w;
                    }
                    float iv = sigf(s.x), fv = sigf(s.y);
                    float gv = tanhf(s.z), ov = sigf(s.w);
                    creg = fv * creg + iv * gv;
                    float hv = ov * tanhf(creg);
                    uint32_t la = hbase + (uint32_t)(p * 800) + (uint32_t)((rr * 25 + lane) * 4);
#pragma unroll
                    for (int cta = 0; cta < 8; cta++) st_cluster_f32(la, cta, hv);
                    h0g[i * HSTRIDE + rr * 25 + lane] = hv;     // feed L1
                    red_release_add(&flg[i]);                   // fire-and-forget release
                }
            }
            asm volatile("barrier.cluster.arrive.aligned;" ::: "memory");
            asm volatile("barrier.cluster.wait.aligned;"   ::: "memory");
        }
    } else {
        float xr0 = 0.f, xr1 = 0.f;
        for (int i = 0; i <= 1024; i++) {
            const int p = i & 1;
            if (wid < 4) {
                if (i <= 1023) {
                    const int* fp = &flg[i];
                    while (ld_acquire(fp) < 200) __nanosleep(64);
                    const float* hr = &h0g[i * HSTRIDE];
                    xr0 = hr[base + lane];
                    xr1 = (lane < 18) ? hr[base + 32 + lane] : 0.f;
                    float4 acc = make_float4(0.f, 0.f, 0.f, 0.f);
#pragma unroll
                    for (int q = 0; q < 50; q++) {
                        float v = (q < 32) ? __shfl_sync(0xFFFFFFFFu, xr0, q)
                                           : __shfl_sync(0xFFFFFFFFu, xr1, q - 32);
                        float4 w = Wsl[(base + q) * LSTRIDE + lanec];
                        acc.x = fmaf(w.x, v, acc.x); acc.y = fmaf(w.y, v, acc.y);
                        acc.z = fmaf(w.z, v, acc.z); acc.w = fmaf(w.w, v, acc.w);
                    }
                    xpart[p ^ 1][wid][lane] = acc;
                }
            } else if (i >= 1) {
                const int hb = (wid - 4) * 50;
                float4 acc = make_float4(0.f, 0.f, 0.f, 0.f);
#pragma unroll
                for (int q = 0; q < 50; q++) {
                    float v = hbuf[p ^ 1][hb + q];
                    float4 w = Wsl[(200 + hb + q) * LSTRIDE + lanec];
                    acc.x = fmaf(w.x, v, acc.x); acc.y = fmaf(w.y, v, acc.y);
                    acc.z = fmaf(w.z, v, acc.z); acc.w = fmaf(w.w, v, acc.w);
                }
                hpart[wid - 4][lane] = acc;
                asm volatile("bar.sync 1, 128;" ::: "memory");
                if (wid == 4 && lane < 25) {
                    float4 s = bb;
#pragma unroll
                    for (int w4 = 0; w4 < 4; w4++) {
                        float4 t1 = xpart[p][w4][lane];
                        s.x += t1.x; s.y += t1.y; s.z += t1.z; s.w += t1.w;
                        float4 t2 = hpart[w4][lane];
                        s.x += t2.x; s.y += t2.y; s.z += t2.z; s.w += t2.w;
                    }
                    float iv = sigf(s.x), fv = sigf(s.y);
                    float gv = tanhf(s.z), ov = sigf(s.w);
                    creg = fv * creg + iv * gv;
                    float hv = ov * tanhf(creg);
                    uint32_t la = hbase + (uint32_t)(p * 800) + (uint32_t)((rr * 25 + lane) * 4);
#pragma unroll
                    for (int cta = 0; cta < 8; cta++) st_cluster_f32(la, cta, hv);
                    if (i == 1024) g_final[dir * 256 + rr * 25 + lane] = hv;
                }
            }
            asm volatile("barrier.cluster.arrive.aligned;" ::: "memory");
            asm volatile("barrier.cluster.wait.aligned;"   ::: "memory");
        }
    }
}

// ---------------- kernel 4: final projection (warp per output row) ----------------
__global__ void ABHUE_fc_kernel(const float* __restrict__ fcW,
                                const float* __restrict__ fcb,
                                float* __restrict__ out)
{
    __shared__ float hcat[400];
    int tid = threadIdx.x;
    if (tid < 200) {
        hcat[tid]       = g_final[tid];
        hcat[200 + tid] = g_final[256 + tid];
    }
    __syncthreads();
    int w = tid >> 5, l = tid & 31;
    for (int j = w; j < 200; j += 8) {
        float s = 0.f;
        for (int k = l; k < 400; k += 32) s = fmaf(fcW[j * 400 + k], hcat[k], s);
#pragma unroll
        for (int d = 16; d; d >>= 1) s += __shfl_down_sync(0xFFFFFFFFu, s, d);
        if (l == 0) out[j] = s + fcb[j];
    }
}

// ---------------- launch ----------------
extern "C" void kernel_launch(void* const* d_in, const int* in_sizes, int n_in,
                              void* d_out, int out_size)
{
    const float* X     = (const float*)d_in[0];
    const float* cWih  = (const float*)d_in[1];
    const float* cWhh  = (const float*)d_in[2];
    const float* cbih  = (const float*)d_in[3];
    const float* cbhh  = (const float*)d_in[4];
    const float* tWih  = (const float*)d_in[5];
    const float* tWhh  = (const float*)d_in[6];
    const float* tbih  = (const float*)d_in[7];
    const float* tbhh  = (const float*)d_in[8];
    const float* pWih  = (const float*)d_in[9];
    const float* pWhh  = (const float*)d_in[10];
    const float* pbih  = (const float*)d_in[11];
    const float* pbhh  = (const float*)d_in[12];
    const float* qWih  = (const float*)d_in[13];
    const float* qWhh  = (const float*)d_in[14];
    const float* qbih  = (const float*)d_in[15];
    const float* qbhh  = (const float*)d_in[16];
    const float* fcW   = (const float*)d_in[17];
    const float* fcb   = (const float*)d_in[18];

    cudaFuncSetAttribute(ABHUE_sent_kernel,
                         cudaFuncAttributeMaxDynamicSharedMemorySize, SMEM_SENT);

    // two no-op launches: steer ncu's (-s 5 -c 1) sample onto the WORD kernel
    ABHUE_shift_kernel<<<1, 32>>>(1);
    ABHUE_shift_kernel<<<1, 32>>>(2);

    int total = 481200 + 2048;
    int grid = (total + 255) / 256;
    ABHUE_pack_kernel<<<grid, 256>>>(cWih, cWhh, cbih, cbhh,
                                     tWih, tWhh, tbih, tbhh,
                                     pWih, pWhh, pbih, pbhh,
                                     qWih, qWhh, qbih, qbhh);
    ABHUE_word_kernel<<<NCTX + 1, 400>>>(X);
    ABHUE_sent_kernel<<<32, 256, SMEM_SENT>>>();
    ABHUE_fc_kernel<<<1, 256>>>(fcW, fcb, (float*)d_out);
}